// round 1
// baseline (speedup 1.0000x reference)
#include <cuda_runtime.h>
#include <math.h>

#define BB 16
#define LL 200
#define HH 128
#define NHH 4
#define HSS 32
#define NBB 2
#define M_TOT (BB*LL)          // 3200
#define MH (M_TOT*HH)          // 409600
#define NEGVAL (-4294967295.0f)
#define LN_EPS 1e-8f

// Scratch: 8 buffers of [B*L*H] floats (13.1 MB total)
__device__ float d_scratch[8 * MH];

// ---------------------------------------------------------------------------
// Embedding: seqs[b,l,:] = item_emb[log_seqs[b,l]] * sqrt(H) * (idx != 0)
// ---------------------------------------------------------------------------
__global__ void embed_kernel(const int* __restrict__ log_seqs,
                             const float* __restrict__ item_emb,
                             float* __restrict__ seqs)
{
    int i = blockIdx.x * blockDim.x + threadIdx.x;
    if (i >= MH) return;
    int row = i >> 7;
    int hc  = i & 127;
    int item = log_seqs[row];
    float v = item_emb[item * HH + hc] * 11.313708498984760390f; // sqrt(128)
    seqs[i] = (item == 0) ? 0.0f : v;
}

// ---------------------------------------------------------------------------
// LayerNorm (optionally fused residual add): out = LN(in + resid) * g + b
// One block per row, 128 threads.
// ---------------------------------------------------------------------------
__global__ void ln_kernel(const float* __restrict__ in,
                          const float* __restrict__ resid,
                          const float* __restrict__ g,
                          const float* __restrict__ bta,
                          float* __restrict__ out)
{
    int row = blockIdx.x;
    int t = threadIdx.x;
    float x = in[row * HH + t];
    if (resid) x += resid[row * HH + t];

    __shared__ float red[4];
    float s = x;
    #pragma unroll
    for (int o = 16; o; o >>= 1) s += __shfl_xor_sync(0xffffffffu, s, o);
    if ((t & 31) == 0) red[t >> 5] = s;
    __syncthreads();
    float m = (red[0] + red[1] + red[2] + red[3]) * (1.0f / HH);
    float d = x - m;
    float s2 = d * d;
    #pragma unroll
    for (int o = 16; o; o >>= 1) s2 += __shfl_xor_sync(0xffffffffu, s2, o);
    __syncthreads();
    if ((t & 31) == 0) red[t >> 5] = s2;
    __syncthreads();
    float v = (red[0] + red[1] + red[2] + red[3]) * (1.0f / HH);
    out[row * HH + t] = d * rsqrtf(v + LN_EPS) * g[t] + bta[t];
}

// ---------------------------------------------------------------------------
// GEMM: C[m,n] = act( sum_k A[m,k]*W[n,k] + bias[n] (+ posadd[(m%L),n])
//                    (+ resid[m,n]) ) * (padidx ? (padidx[m]!=0) : 1)
// M = 3200, N = K = 128. 16 rows per block, 256 threads,
// thread computes 4 rows x 2 cols (cols c and c+64, conflict-free).
// ---------------------------------------------------------------------------
__global__ void gemm_kernel(const float* __restrict__ A,
                            const float* __restrict__ W,
                            const float* __restrict__ bias,
                            const float* __restrict__ posadd,
                            const float* __restrict__ resid,
                            const int*  __restrict__ padidx,
                            float* __restrict__ C,
                            int relu)
{
    const int ROWS = 16;
    __shared__ float As[ROWS][HH];   // 8 KB
    __shared__ float Ws[HH][33];     // k-tile of W, 16.9 KB, padded

    int tid  = threadIdx.x;          // 256
    int row0 = blockIdx.x * ROWS;

    #pragma unroll
    for (int idx = tid; idx < ROWS * HH; idx += 256)
        As[idx >> 7][idx & 127] = A[(row0 + (idx >> 7)) * HH + (idx & 127)];

    int c  = tid & 63;               // column base (pair: c, c+64)
    int rg = tid >> 6;               // 0..3 (row group of 4)
    float acc[4][2] = {};

    for (int k0 = 0; k0 < HH; k0 += 32) {
        __syncthreads();
        #pragma unroll
        for (int idx = tid; idx < HH * 32; idx += 256) {
            int n = idx >> 5, kk = idx & 31;
            Ws[n][kk] = W[n * HH + k0 + kk];
        }
        __syncthreads();
        #pragma unroll
        for (int kk = 0; kk < 32; kk++) {
            float w0 = Ws[c][kk];
            float w1 = Ws[c + 64][kk];
            #pragma unroll
            for (int r = 0; r < 4; r++) {
                float a = As[rg * 4 + r][k0 + kk];
                acc[r][0] += a * w0;
                acc[r][1] += a * w1;
            }
        }
    }

    #pragma unroll
    for (int r = 0; r < 4; r++) {
        int m = row0 + rg * 4 + r;
        int lrow = m % LL;
        float pmask = padidx ? (padidx[m] != 0 ? 1.0f : 0.0f) : 1.0f;
        #pragma unroll
        for (int j = 0; j < 2; j++) {
            int n = c + j * 64;
            float v = acc[r][j] + bias[n];
            if (posadd) v += posadd[lrow * HH + n];
            if (resid)  v += resid[m * HH + n];
            if (relu)   v = fmaxf(v, 0.0f);
            C[m * HH + n] = v * pmask;
        }
    }
}

// ---------------------------------------------------------------------------
// Attention: one block per (b, h, q). 128 threads.
// score[k] = Q . (K'[b,k] + tm_K[t[b,q,k]]) * scale   (K' has pos_K folded in)
// out[d]   = sum_k p[k] * (V'[b,k,d] + tm_V[t[b,q,k],d])
// Masked entries get NEG; pad-query rows reproduce the uniform softmax.
// ---------------------------------------------------------------------------
__global__ void attn_kernel(const float* __restrict__ Qb,
                            const float* __restrict__ Kb,
                            const float* __restrict__ Vb,
                            const int*  __restrict__ tmat,
                            const float* __restrict__ tmK,
                            const float* __restrict__ tmV,
                            const int*  __restrict__ log_seqs,
                            float* __restrict__ outp)
{
    int qi = blockIdx.x;
    int h  = blockIdx.y;
    int b  = blockIdx.z;
    int tid = threadIdx.x;       // 128

    __shared__ float qsh[HSS];
    __shared__ float s[LL];
    __shared__ int   tsh[LL];
    __shared__ float red[8];
    __shared__ float part[4][HSS];

    const int rowq = b * LL + qi;
    if (tid < HSS) qsh[tid] = Qb[rowq * HH + h * HSS + tid];
    __syncthreads();

    bool padq = (log_seqs[rowq] == 0);
    const float scale = 0.17677669529663687f; // 1/sqrt(32)

    // --- scores ---
    for (int k = tid; k < LL; k += 128) {
        int t = tmat[rowq * LL + k];
        tsh[k] = t;
        float sc;
        if (padq || k > qi) {
            sc = NEGVAL;
        } else {
            const float* Kp = Kb + (b * LL + k) * HH + h * HSS;
            const float* Tp = tmK + t * HH + h * HSS;
            float acc = 0.0f;
            #pragma unroll
            for (int d = 0; d < HSS; d++) acc += qsh[d] * (Kp[d] + Tp[d]);
            sc = acc * scale;
        }
        s[k] = sc;
    }
    __syncthreads();

    // --- softmax (max) ---
    float mx = -INFINITY;
    for (int k = tid; k < LL; k += 128) mx = fmaxf(mx, s[k]);
    #pragma unroll
    for (int o = 16; o; o >>= 1) mx = fmaxf(mx, __shfl_xor_sync(0xffffffffu, mx, o));
    if ((tid & 31) == 0) red[tid >> 5] = mx;
    __syncthreads();
    mx = fmaxf(fmaxf(red[0], red[1]), fmaxf(red[2], red[3]));

    // --- softmax (exp + sum) ---
    float sum = 0.0f;
    for (int k = tid; k < LL; k += 128) {
        float e = expf(s[k] - mx);
        s[k] = e;
        sum += e;
    }
    #pragma unroll
    for (int o = 16; o; o >>= 1) sum += __shfl_xor_sync(0xffffffffu, sum, o);
    __syncthreads();
    if ((tid & 31) == 0) red[4 + (tid >> 5)] = sum;
    __syncthreads();
    float inv = 1.0f / (red[4] + red[5] + red[6] + red[7]);

    // --- output: 32 d-lanes x 4 k-groups ---
    int d2 = tid & 31;
    int kg = tid >> 5;
    int kmax = padq ? LL : (qi + 1);
    float acc = 0.0f;
    for (int k = kg; k < kmax; k += 4) {
        float p = s[k];
        const float* Vp = Vb + (b * LL + k) * HH + h * HSS;
        const float* Tp = tmV + tsh[k] * HH + h * HSS;
        acc += p * (Vp[d2] + Tp[d2]);
    }
    part[kg][d2] = acc;
    __syncthreads();
    if (tid < HSS) {
        float o = (part[0][tid] + part[1][tid] + part[2][tid] + part[3][tid]) * inv;
        outp[rowq * HH + h * HSS + tid] = o;
    }
}

// ---------------------------------------------------------------------------
// Logits: out[row] = feats[row] . emb[pos[row]], out[M_TOT+row] = . emb[neg]
// ---------------------------------------------------------------------------
__global__ void logits_kernel(const float* __restrict__ feats,
                              const float* __restrict__ item_emb,
                              const int* __restrict__ pos_seqs,
                              const int* __restrict__ neg_seqs,
                              float* __restrict__ out)
{
    int row = blockIdx.x;
    int t = threadIdx.x;
    float f = feats[row * HH + t];
    float p = f * item_emb[pos_seqs[row] * HH + t];
    float n = f * item_emb[neg_seqs[row] * HH + t];
    __shared__ float red[8];
    #pragma unroll
    for (int o = 16; o; o >>= 1) {
        p += __shfl_xor_sync(0xffffffffu, p, o);
        n += __shfl_xor_sync(0xffffffffu, n, o);
    }
    if ((t & 31) == 0) { red[t >> 5] = p; red[4 + (t >> 5)] = n; }
    __syncthreads();
    if (t == 0) out[row]         = red[0] + red[1] + red[2] + red[3];
    if (t == 1) out[M_TOT + row] = red[4] + red[5] + red[6] + red[7];
}

// ---------------------------------------------------------------------------
extern "C" void kernel_launch(void* const* d_in, const int* in_sizes, int n_in,
                              void* d_out, int out_size)
{
    const int*   log_seqs = (const int*)  d_in[0];
    const int*   tmat     = (const int*)  d_in[1];
    const int*   pos_seqs = (const int*)  d_in[2];
    const int*   neg_seqs = (const int*)  d_in[3];
    const float* item_emb = (const float*)d_in[5];
    const float* pos_K    = (const float*)d_in[6];
    const float* pos_V    = (const float*)d_in[7];
    const float* tm_K     = (const float*)d_in[8];
    const float* tm_V     = (const float*)d_in[9];
    const float* Wq = (const float*)d_in[10]; const float* bq = (const float*)d_in[11];
    const float* Wk = (const float*)d_in[12]; const float* bk = (const float*)d_in[13];
    const float* Wv = (const float*)d_in[14]; const float* bv = (const float*)d_in[15];
    const float* ln1_g = (const float*)d_in[16]; const float* ln1_b = (const float*)d_in[17];
    const float* ln2_g = (const float*)d_in[18]; const float* ln2_b = (const float*)d_in[19];
    const float* W1 = (const float*)d_in[20]; const float* b1 = (const float*)d_in[21];
    const float* W2 = (const float*)d_in[22]; const float* b2 = (const float*)d_in[23];
    const float* lnf_g = (const float*)d_in[24]; const float* lnf_b = (const float*)d_in[25];
    float* out = (float*)d_out;

    float* S = nullptr;
    cudaGetSymbolAddress((void**)&S, d_scratch);
    float* seqs  = S + 0 * MH;
    float* Qin   = S + 1 * MH;
    float* Qb    = S + 2 * MH;
    float* Kb    = S + 3 * MH;
    float* Vb    = S + 4 * MH;
    float* attn  = S + 5 * MH;
    float* seqs2 = S + 6 * MH;
    float* hmid  = S + 7 * MH;

    embed_kernel<<<(MH + 255) / 256, 256>>>(log_seqs, item_emb, seqs);

    for (int i = 0; i < NBB; i++) {
        ln_kernel<<<M_TOT, 128>>>(seqs, nullptr, ln1_g + i * HH, ln1_b + i * HH, Qin);
        gemm_kernel<<<M_TOT / 16, 256>>>(Qin,  Wq + i * HH * HH, bq + i * HH,
                                         nullptr, nullptr, nullptr, Qb, 0);
        gemm_kernel<<<M_TOT / 16, 256>>>(seqs, Wk + i * HH * HH, bk + i * HH,
                                         pos_K, nullptr, nullptr, Kb, 0);
        gemm_kernel<<<M_TOT / 16, 256>>>(seqs, Wv + i * HH * HH, bv + i * HH,
                                         pos_V, nullptr, nullptr, Vb, 0);
        dim3 ag(LL, NHH, BB);
        attn_kernel<<<ag, 128>>>(Qb, Kb, Vb, tmat, tm_K, tm_V, log_seqs, attn);
        ln_kernel<<<M_TOT, 128>>>(attn, Qin, ln2_g + i * HH, ln2_b + i * HH, seqs2);
        gemm_kernel<<<M_TOT / 16, 256>>>(seqs2, W1 + i * HH * HH, b1 + i * HH,
                                         nullptr, nullptr, nullptr, hmid, 1);
        gemm_kernel<<<M_TOT / 16, 256>>>(hmid, W2 + i * HH * HH, b2 + i * HH,
                                         nullptr, seqs2, log_seqs, seqs, 0);
    }

    // final LN (reuse Qin as feats) + logits
    ln_kernel<<<M_TOT, 128>>>(seqs, nullptr, lnf_g, lnf_b, Qin);
    logits_kernel<<<M_TOT, 128>>>(Qin, item_emb, pos_seqs, neg_seqs, out);
}

// round 3
// speedup vs baseline: 1.5790x; 1.5790x over previous
#include <cuda_runtime.h>
#include <math.h>

#define BB 16
#define LL 200
#define HH 128
#define NHH 4
#define HSS 32
#define NBB 2
#define M_TOT (BB*LL)          // 3200
#define MH (M_TOT*HH)          // 409600
#define NEGVAL (-4294967295.0f)
#define LN_EPS 1e-8f
#define QSPLIT 2
#define KROW 36                // padded shared row stride (floats)
#define TROWS 257

// Scratch: 8 buffers of [B*L*H] floats + 10 transposed 128x128 weights
__device__ float d_scratch[8 * MH];
__device__ float d_wt[10 * HH * HH];

// ---------------------------------------------------------------------------
__global__ void embed_kernel(const int* __restrict__ log_seqs,
                             const float* __restrict__ item_emb,
                             float* __restrict__ seqs)
{
    int i = blockIdx.x * blockDim.x + threadIdx.x;
    if (i >= MH) return;
    int row = i >> 7;
    int hc  = i & 127;
    int item = log_seqs[row];
    float v = item_emb[item * HH + hc] * 11.313708498984760390f; // sqrt(128)
    seqs[i] = (item == 0) ? 0.0f : v;
}

// ---------------------------------------------------------------------------
// Transpose the 10 weight matrices [n][k] -> WT [k][n]
// matid: 0-1 Wq, 2-3 Wk, 4-5 Wv, 6-7 W1, 8-9 W2
// ---------------------------------------------------------------------------
__global__ void transpose_w(const float* __restrict__ Wq, const float* __restrict__ Wk,
                            const float* __restrict__ Wv, const float* __restrict__ W1,
                            const float* __restrict__ W2, float* __restrict__ WT)
{
    __shared__ float t[32][33];
    int m = blockIdx.z;
    const float* src;
    switch (m >> 1) {
        case 0: src = Wq; break;
        case 1: src = Wk; break;
        case 2: src = Wv; break;
        case 3: src = W1; break;
        default: src = W2; break;
    }
    src += (m & 1) * HH * HH;
    float* dst = WT + m * HH * HH;

    int x  = blockIdx.x * 32 + threadIdx.x;   // k index (src col)
    int y0 = blockIdx.y * 32;                 // n base (src row)
    for (int i = threadIdx.y; i < 32; i += 8)
        t[i][threadIdx.x] = src[(y0 + i) * HH + x];
    __syncthreads();
    int xo  = blockIdx.y * 32 + threadIdx.x;  // n index (dst col)
    int yo0 = blockIdx.x * 32;                // k base (dst row)
    for (int i = threadIdx.y; i < 32; i += 8)
        dst[(yo0 + i) * HH + xo] = t[threadIdx.x][i];
}

// ---------------------------------------------------------------------------
// LayerNorm (optionally fused residual): out = LN(in + resid) * g + b
// ---------------------------------------------------------------------------
__global__ void ln_kernel(const float* __restrict__ in,
                          const float* __restrict__ resid,
                          const float* __restrict__ g,
                          const float* __restrict__ bta,
                          float* __restrict__ out)
{
    int row = blockIdx.x;
    int t = threadIdx.x;
    float x = in[row * HH + t];
    if (resid) x += resid[row * HH + t];

    __shared__ float red[4];
    float s = x;
    #pragma unroll
    for (int o = 16; o; o >>= 1) s += __shfl_xor_sync(0xffffffffu, s, o);
    if ((t & 31) == 0) red[t >> 5] = s;
    __syncthreads();
    float m = (red[0] + red[1] + red[2] + red[3]) * (1.0f / HH);
    float d = x - m;
    float s2 = d * d;
    #pragma unroll
    for (int o = 16; o; o >>= 1) s2 += __shfl_xor_sync(0xffffffffu, s2, o);
    __syncthreads();
    if ((t & 31) == 0) red[t >> 5] = s2;
    __syncthreads();
    float v = (red[0] + red[1] + red[2] + red[3]) * (1.0f / HH);
    out[row * HH + t] = d * rsqrtf(v + LN_EPS) * g[t] + bta[t];
}

// ---------------------------------------------------------------------------
// GEMM: C = act(A @ WT + bias (+posadd) (+resid)) * padmask
// A [3200,128], WT [128(k)][128(n)] pre-transposed. 32 rows/block, 256 thr,
// thread computes 4 rows x 4 cols (one float4 of columns).
// ---------------------------------------------------------------------------
__global__ void __launch_bounds__(256)
gemm3(const float* __restrict__ A, const float* __restrict__ WT,
      const float* __restrict__ bias, const float* __restrict__ posadd,
      const float* __restrict__ resid, const int* __restrict__ padidx,
      float* __restrict__ C, int relu)
{
    __shared__ float As[32 * HH];    // 16 KB
    int tid  = threadIdx.x;
    int row0 = blockIdx.x * 32;

    #pragma unroll
    for (int idx = tid; idx < 32 * 32; idx += 256)
        ((float4*)As)[idx] = ((const float4*)(A + row0 * HH))[idx];
    __syncthreads();

    int cg = tid & 31;   // float4 column group: cols 4cg..4cg+3
    int rg = tid >> 5;   // row group: rows rg*4..rg*4+3
    float4 acc[4];
    #pragma unroll
    for (int i = 0; i < 4; i++) acc[i] = make_float4(0.f, 0.f, 0.f, 0.f);

    const float4* W4 = (const float4*)WT;
    #pragma unroll 4
    for (int k4 = 0; k4 < 32; k4++) {
        float4 w0 = W4[(4 * k4 + 0) * 32 + cg];
        float4 w1 = W4[(4 * k4 + 1) * 32 + cg];
        float4 w2 = W4[(4 * k4 + 2) * 32 + cg];
        float4 w3 = W4[(4 * k4 + 3) * 32 + cg];
        #pragma unroll
        for (int i = 0; i < 4; i++) {
            float4 a = ((const float4*)(As + (rg * 4 + i) * HH))[k4];
            acc[i].x += a.x * w0.x + a.y * w1.x + a.z * w2.x + a.w * w3.x;
            acc[i].y += a.x * w0.y + a.y * w1.y + a.z * w2.y + a.w * w3.y;
            acc[i].z += a.x * w0.z + a.y * w1.z + a.z * w2.z + a.w * w3.z;
            acc[i].w += a.x * w0.w + a.y * w1.w + a.z * w2.w + a.w * w3.w;
        }
    }

    float4 bs = ((const float4*)bias)[cg];
    #pragma unroll
    for (int i = 0; i < 4; i++) {
        int m = row0 + rg * 4 + i;
        float4 v = acc[i];
        v.x += bs.x; v.y += bs.y; v.z += bs.z; v.w += bs.w;
        if (posadd) {
            float4 p = ((const float4*)(posadd + (m % LL) * HH))[cg];
            v.x += p.x; v.y += p.y; v.z += p.z; v.w += p.w;
        }
        if (resid) {
            float4 r = ((const float4*)(resid + m * HH))[cg];
            v.x += r.x; v.y += r.y; v.z += r.z; v.w += r.w;
        }
        if (relu) {
            v.x = fmaxf(v.x, 0.f); v.y = fmaxf(v.y, 0.f);
            v.z = fmaxf(v.z, 0.f); v.w = fmaxf(v.w, 0.f);
        }
        if (padidx && padidx[m] == 0) v = make_float4(0.f, 0.f, 0.f, 0.f);
        ((float4*)(C + m * HH))[cg] = v;
    }
}

// ---------------------------------------------------------------------------
// Attention: one block per (q-chunk, h, b). 256 threads. All tables in smem.
// score[k] = Q.(K'[k] + tm_K[t]) * scale, out = sum p*(V'[k] + tm_V[t]).
// ---------------------------------------------------------------------------
__global__ void __launch_bounds__(256)
attn_kernel(const float* __restrict__ Qb,
            const float* __restrict__ Kb,
            const float* __restrict__ Vb,
            const int*  __restrict__ tmat,
            const float* __restrict__ tmKg,
            const float* __restrict__ tmVg,
            const int*  __restrict__ log_seqs,
            float* __restrict__ outp)
{
    extern __shared__ float sm[];
    float* Ksh  = sm;                       // 200*36 = 7200
    float* Vsh  = Ksh + LL * KROW;          // 7200
    float* tmKs = Vsh + LL * KROW;          // 257*36 = 9252
    float* tmVs = tmKs + TROWS * KROW;      // 9252
    float* qsh  = tmVs + TROWS * KROW;      // 32
    float* s    = qsh + 32;                 // 200
    float* red  = s + LL;                   // 16
    float* part = red + 16;                 // 256
    int*   tsh  = (int*)(part + 256);       // 200

    int qc = blockIdx.x;
    int h  = blockIdx.y;
    int b  = blockIdx.z;
    int tid = threadIdx.x;

    // stage K', V' head slices
    for (int idx = tid; idx < LL * 8; idx += 256) {
        int r = idx >> 3, d4 = idx & 7;
        ((float4*)(Ksh + r * KROW))[d4] =
            ((const float4*)(Kb + (b * LL + r) * HH + h * HSS))[d4];
        ((float4*)(Vsh + r * KROW))[d4] =
            ((const float4*)(Vb + (b * LL + r) * HH + h * HSS))[d4];
    }
    // stage tm_K, tm_V head slices
    for (int idx = tid; idx < TROWS * 8; idx += 256) {
        int r = idx >> 3, d4 = idx & 7;
        ((float4*)(tmKs + r * KROW))[d4] =
            ((const float4*)(tmKg + r * HH + h * HSS))[d4];
        ((float4*)(tmVs + r * KROW))[d4] =
            ((const float4*)(tmVg + r * HH + h * HSS))[d4];
    }
    __syncthreads();

    const float scale = 0.17677669529663687f; // 1/sqrt(32)

    for (int j = 0; j < LL / QSPLIT; j++) {
        int q = qc + QSPLIT * j;
        int rowq = b * LL + q;
        if (tid < HSS) qsh[tid] = Qb[rowq * HH + h * HSS + tid];
        if (tid < LL)  tsh[tid] = tmat[rowq * LL + tid];
        bool padq = (log_seqs[rowq] == 0);
        __syncthreads();

        // scores
        if (tid < LL) {
            int k = tid;
            float sc = NEGVAL;
            if (!padq && k <= q) {
                const float4* kp = (const float4*)(Ksh + k * KROW);
                const float4* tp = (const float4*)(tmKs + tsh[k] * KROW);
                const float4* qp = (const float4*)qsh;
                float acc = 0.f;
                #pragma unroll
                for (int d4 = 0; d4 < 8; d4++) {
                    float4 qv = qp[d4], kv = kp[d4], tv = tp[d4];
                    acc += qv.x * (kv.x + tv.x) + qv.y * (kv.y + tv.y)
                         + qv.z * (kv.z + tv.z) + qv.w * (kv.w + tv.w);
                }
                sc = acc * scale;
            }
            s[tid] = sc;
        }
        __syncthreads();

        // softmax max
        float m = (tid < LL) ? s[tid] : -INFINITY;
        #pragma unroll
        for (int o = 16; o; o >>= 1) m = fmaxf(m, __shfl_xor_sync(0xffffffffu, m, o));
        if ((tid & 31) == 0) red[tid >> 5] = m;
        __syncthreads();
        float mx = red[0];
        #pragma unroll
        for (int w = 1; w < 8; w++) mx = fmaxf(mx, red[w]);

        // exp + sum (each thread touches only its own s[tid])
        float e = 0.f;
        if (tid < LL) { e = __expf(s[tid] - mx); s[tid] = e; }
        float sum = e;
        #pragma unroll
        for (int o = 16; o; o >>= 1) sum += __shfl_xor_sync(0xffffffffu, sum, o);
        if ((tid & 31) == 0) red[8 + (tid >> 5)] = sum;
        __syncthreads();
        float tot = red[8];
        #pragma unroll
        for (int w = 1; w < 8; w++) tot += red[8 + w];
        float inv = 1.0f / tot;

        // value accumulation: warp g handles keys k = g, g+8, ...
        int d = tid & 31, g = tid >> 5;
        int kmax = padq ? LL : (q + 1);
        float acc = 0.f;
        for (int k = g; k < kmax; k += 8) {
            float p = s[k];
            acc += p * (Vsh[k * KROW + d] + tmVs[tsh[k] * KROW + d]);
        }
        part[g * 32 + d] = acc;
        __syncthreads();
        if (tid < HSS) {
            float o = 0.f;
            #pragma unroll
            for (int g2 = 0; g2 < 8; g2++) o += part[g2 * 32 + tid];
            outp[rowq * HH + h * HSS + tid] = o * inv;
        }
        __syncthreads();
    }
}

// ---------------------------------------------------------------------------
__global__ void logits_kernel(const float* __restrict__ feats,
                              const float* __restrict__ item_emb,
                              const int* __restrict__ pos_seqs,
                              const int* __restrict__ neg_seqs,
                              float* __restrict__ out)
{
    int row = blockIdx.x;
    int t = threadIdx.x;
    float f = feats[row * HH + t];
    float p = f * item_emb[pos_seqs[row] * HH + t];
    float n = f * item_emb[neg_seqs[row] * HH + t];
    __shared__ float red[8];
    #pragma unroll
    for (int o = 16; o; o >>= 1) {
        p += __shfl_xor_sync(0xffffffffu, p, o);
        n += __shfl_xor_sync(0xffffffffu, n, o);
    }
    if ((t & 31) == 0) { red[t >> 5] = p; red[4 + (t >> 5)] = n; }
    __syncthreads();
    if (t == 0) out[row]         = red[0] + red[1] + red[2] + red[3];
    if (t == 1) out[M_TOT + row] = red[4] + red[5] + red[6] + red[7];
}

// ---------------------------------------------------------------------------
extern "C" void kernel_launch(void* const* d_in, const int* in_sizes, int n_in,
                              void* d_out, int out_size)
{
    const int*   log_seqs = (const int*)  d_in[0];
    const int*   tmat     = (const int*)  d_in[1];
    const int*   pos_seqs = (const int*)  d_in[2];
    const int*   neg_seqs = (const int*)  d_in[3];
    const float* item_emb = (const float*)d_in[5];
    const float* pos_K    = (const float*)d_in[6];
    const float* pos_V    = (const float*)d_in[7];
    const float* tm_K     = (const float*)d_in[8];
    const float* tm_V     = (const float*)d_in[9];
    const float* Wq = (const float*)d_in[10]; const float* bq = (const float*)d_in[11];
    const float* Wk = (const float*)d_in[12]; const float* bk = (const float*)d_in[13];
    const float* Wv = (const float*)d_in[14]; const float* bv = (const float*)d_in[15];
    const float* ln1_g = (const float*)d_in[16]; const float* ln1_b = (const float*)d_in[17];
    const float* ln2_g = (const float*)d_in[18]; const float* ln2_b = (const float*)d_in[19];
    const float* W1 = (const float*)d_in[20]; const float* b1 = (const float*)d_in[21];
    const float* W2 = (const float*)d_in[22]; const float* b2 = (const float*)d_in[23];
    const float* lnf_g = (const float*)d_in[24]; const float* lnf_b = (const float*)d_in[25];
    float* out = (float*)d_out;

    float* S = nullptr;
    cudaGetSymbolAddress((void**)&S, d_scratch);
    float* WTbase = nullptr;
    cudaGetSymbolAddress((void**)&WTbase, d_wt);

    float* seqs  = S + 0 * MH;
    float* Qin   = S + 1 * MH;
    float* Qb    = S + 2 * MH;
    float* Kb    = S + 3 * MH;
    float* Vb    = S + 4 * MH;
    float* attn  = S + 5 * MH;
    float* seqs2 = S + 6 * MH;
    float* hmid  = S + 7 * MH;

    const int ATTN_SMEM = (2 * LL * KROW + 2 * TROWS * KROW + 32 + LL + 16 + 256 + LL) * 4;
    cudaFuncSetAttribute(attn_kernel, cudaFuncAttributeMaxDynamicSharedMemorySize, ATTN_SMEM);

    transpose_w<<<dim3(4, 4, 10), dim3(32, 8)>>>(Wq, Wk, Wv, W1, W2, WTbase);
    embed_kernel<<<(MH + 255) / 256, 256>>>(log_seqs, item_emb, seqs);

    for (int i = 0; i < NBB; i++) {
        ln_kernel<<<M_TOT, 128>>>(seqs, nullptr, ln1_g + i * HH, ln1_b + i * HH, Qin);
        gemm3<<<M_TOT / 32, 256>>>(Qin,  WTbase + (0 + i) * HH * HH, bq + i * HH,
                                   nullptr, nullptr, nullptr, Qb, 0);
        gemm3<<<M_TOT / 32, 256>>>(seqs, WTbase + (2 + i) * HH * HH, bk + i * HH,
                                   pos_K, nullptr, nullptr, Kb, 0);
        gemm3<<<M_TOT / 32, 256>>>(seqs, WTbase + (4 + i) * HH * HH, bv + i * HH,
                                   pos_V, nullptr, nullptr, Vb, 0);
        attn_kernel<<<dim3(QSPLIT, NHH, BB), 256, ATTN_SMEM>>>(
            Qb, Kb, Vb, tmat, tm_K, tm_V, log_seqs, attn);
        ln_kernel<<<M_TOT, 128>>>(attn, Qin, ln2_g + i * HH, ln2_b + i * HH, seqs2);
        gemm3<<<M_TOT / 32, 256>>>(seqs2, WTbase + (6 + i) * HH * HH, b1 + i * HH,
                                   nullptr, nullptr, nullptr, hmid, 1);
        gemm3<<<M_TOT / 32, 256>>>(hmid, WTbase + (8 + i) * HH * HH, b2 + i * HH,
                                   nullptr, seqs2, log_seqs, seqs, 0);
    }

    ln_kernel<<<M_TOT, 128>>>(seqs, nullptr, lnf_g, lnf_b, Qin);
    logits_kernel<<<M_TOT, 128>>>(Qin, item_emb, pos_seqs, neg_seqs, out);
}

// round 4
// speedup vs baseline: 2.5601x; 1.6213x over previous
#include <cuda_runtime.h>
#include <math.h>

#define BB 16
#define LL 200
#define HH 128
#define NHH 4
#define HSS 32
#define NBB 2
#define M_TOT (BB*LL)          // 3200
#define MH (M_TOT*HH)          // 409600
#define NEGVAL (-4294967295.0f)
#define LN_EPS 1e-8f
#define KROW 36                // padded shared row stride (floats), float4-aligned
#define TROWS 257
#define FULLM 0xffffffffu
#define WT_OFF(type, layer) (((type)*2+(layer))*HH*HH)

// Scratch buffers + transposed weights
__device__ float d_scratch[8 * MH];
__device__ float d_wt[10 * HH * HH];

// ---------------------------------------------------------------------------
__global__ void embed_kernel(const int* __restrict__ log_seqs,
                             const float* __restrict__ item_emb,
                             float* __restrict__ seqs)
{
    int i = blockIdx.x * blockDim.x + threadIdx.x;
    if (i >= MH) return;
    int row = i >> 7;
    int hc  = i & 127;
    int item = log_seqs[row];
    float v = item_emb[item * HH + hc] * 11.313708498984760390f; // sqrt(128)
    seqs[i] = (item == 0) ? 0.0f : v;
}

// ---------------------------------------------------------------------------
// Transpose the 10 weight matrices [n][k] -> WT [k][n]
// type: 0 Wq, 1 Wk, 2 Wv, 3 W1, 4 W2 ; m = type*2 + layer
// ---------------------------------------------------------------------------
__global__ void transpose_w(const float* __restrict__ Wq, const float* __restrict__ Wk,
                            const float* __restrict__ Wv, const float* __restrict__ W1,
                            const float* __restrict__ W2, float* __restrict__ WT)
{
    __shared__ float t[32][33];
    int m = blockIdx.z;
    const float* src;
    switch (m >> 1) {
        case 0: src = Wq; break;
        case 1: src = Wk; break;
        case 2: src = Wv; break;
        case 3: src = W1; break;
        default: src = W2; break;
    }
    src += (m & 1) * HH * HH;
    float* dst = WT + m * HH * HH;

    int x  = blockIdx.x * 32 + threadIdx.x;
    int y0 = blockIdx.y * 32;
    for (int i = threadIdx.y; i < 32; i += 8)
        t[i][threadIdx.x] = src[(y0 + i) * HH + x];
    __syncthreads();
    int xo  = blockIdx.y * 32 + threadIdx.x;
    int yo0 = blockIdx.x * 32;
    for (int i = threadIdx.y; i < 32; i += 8)
        dst[(yo0 + i) * HH + xo] = t[threadIdx.x][i];
}

// ---------------------------------------------------------------------------
// GEMM core: As [32][128] smem, Ws4 float4-view of WT tile [128][128] smem.
// Thread (cg, rg) computes rows rg*4..+3, col-float4 cg. A reads broadcast.
// ---------------------------------------------------------------------------
__device__ __forceinline__ void gemm_core(const float* As, const float4* Ws4,
                                          int cg, int rg, float4 acc[4])
{
    #pragma unroll 8
    for (int k4 = 0; k4 < 32; k4++) {
        float4 w0 = Ws4[(4 * k4 + 0) * 32 + cg];
        float4 w1 = Ws4[(4 * k4 + 1) * 32 + cg];
        float4 w2 = Ws4[(4 * k4 + 2) * 32 + cg];
        float4 w3 = Ws4[(4 * k4 + 3) * 32 + cg];
        #pragma unroll
        for (int i = 0; i < 4; i++) {
            float4 a = ((const float4*)(As + (rg * 4 + i) * HH))[k4];
            acc[i].x += a.x * w0.x + a.y * w1.x + a.z * w2.x + a.w * w3.x;
            acc[i].y += a.x * w0.y + a.y * w1.y + a.z * w2.y + a.w * w3.y;
            acc[i].z += a.x * w0.z + a.y * w1.z + a.z * w2.z + a.w * w3.z;
            acc[i].w += a.x * w0.w + a.y * w1.w + a.z * w2.w + a.w * w3.w;
        }
    }
}

// LayerNorm a 32x128 tile in shared (in place); optionally also write to gout.
// Warp per row (8 warps cover 32 rows in 4 passes).
__device__ __forceinline__ void ln_tile(float* As, const float* __restrict__ g,
                                        const float* __restrict__ bta,
                                        float* __restrict__ gout, int row0)
{
    int w = threadIdx.x >> 5, lane = threadIdx.x & 31;
    for (int r = w; r < 32; r += 8) {
        float* row = As + r * HH;
        float x0 = row[lane], x1 = row[lane + 32], x2 = row[lane + 64], x3 = row[lane + 96];
        float s = x0 + x1 + x2 + x3;
        #pragma unroll
        for (int o = 16; o; o >>= 1) s += __shfl_xor_sync(FULLM, s, o);
        float m = s * (1.0f / HH);
        float d0 = x0 - m, d1 = x1 - m, d2 = x2 - m, d3 = x3 - m;
        float v = d0 * d0 + d1 * d1 + d2 * d2 + d3 * d3;
        #pragma unroll
        for (int o = 16; o; o >>= 1) v += __shfl_xor_sync(FULLM, v, o);
        float rs = rsqrtf(v * (1.0f / HH) + LN_EPS);
        float y0 = d0 * rs * g[lane]      + bta[lane];
        float y1 = d1 * rs * g[lane + 32] + bta[lane + 32];
        float y2 = d2 * rs * g[lane + 64] + bta[lane + 64];
        float y3 = d3 * rs * g[lane + 96] + bta[lane + 96];
        row[lane] = y0; row[lane + 32] = y1; row[lane + 64] = y2; row[lane + 96] = y3;
        if (gout) {
            float* go = gout + (row0 + r) * HH;
            go[lane] = y0; go[lane + 32] = y1; go[lane + 64] = y2; go[lane + 96] = y3;
        }
    }
}

// ---------------------------------------------------------------------------
// QKV kernel: grid (100, 3). z=0: Q = LN1(seqs)@WqT+bq (also writes Qin).
// z=1: K = seqs@WkT+bk+posK. z=2: V = seqs@WvT+bv+posV.
// ---------------------------------------------------------------------------
__global__ void __launch_bounds__(256)
qkv_kernel(const float* __restrict__ seqs, const float* __restrict__ WTbase, int layer,
           const float* __restrict__ bq, const float* __restrict__ bk,
           const float* __restrict__ bv,
           const float* __restrict__ posK, const float* __restrict__ posV,
           const float* __restrict__ ln_g, const float* __restrict__ ln_b,
           float* __restrict__ Qin, float* __restrict__ Qb,
           float* __restrict__ Kb, float* __restrict__ Vb)
{
    extern __shared__ float sm[];
    float* As = sm;                      // 32*128
    float4* Ws4 = (float4*)(sm + 32 * HH);
    int tid = threadIdx.x;
    int z = blockIdx.y;
    int row0 = blockIdx.x * 32;

    #pragma unroll
    for (int idx = tid; idx < 32 * 32; idx += 256)
        ((float4*)As)[idx] = ((const float4*)(seqs + row0 * HH))[idx];
    const float4* Wsrc = (const float4*)(WTbase + WT_OFF(z, layer));
    #pragma unroll
    for (int idx = tid; idx < 4096; idx += 256)
        Ws4[idx] = Wsrc[idx];
    __syncthreads();
    if (z == 0) {
        ln_tile(As, ln_g, ln_b, Qin, row0);
        __syncthreads();
    }

    int cg = tid & 31, rg = tid >> 5;
    float4 acc[4];
    #pragma unroll
    for (int i = 0; i < 4; i++) acc[i] = make_float4(0.f, 0.f, 0.f, 0.f);
    gemm_core(As, Ws4, cg, rg, acc);

    const float* bias = (z == 0) ? bq : (z == 1) ? bk : bv;
    const float* posadd = (z == 1) ? posK : (z == 2) ? posV : nullptr;
    float* C = (z == 0) ? Qb : (z == 1) ? Kb : Vb;
    float4 bs = ((const float4*)bias)[cg];
    #pragma unroll
    for (int i = 0; i < 4; i++) {
        int m = row0 + rg * 4 + i;
        float4 v = acc[i];
        v.x += bs.x; v.y += bs.y; v.z += bs.z; v.w += bs.w;
        if (posadd) {
            float4 p = ((const float4*)(posadd + (m % LL) * HH))[cg];
            v.x += p.x; v.y += p.y; v.z += p.z; v.w += p.w;
        }
        ((float4*)(C + m * HH))[cg] = v;
    }
}

// ---------------------------------------------------------------------------
// FFN1: seqs2 = LN2(attn + Qin); hmid = relu(seqs2 @ W1T + b1)
// ---------------------------------------------------------------------------
__global__ void __launch_bounds__(256)
ffn1_kernel(const float* __restrict__ attn, const float* __restrict__ Qin,
            const float* __restrict__ WTbase, int layer,
            const float* __restrict__ b1,
            const float* __restrict__ ln_g, const float* __restrict__ ln_b,
            float* __restrict__ seqs2, float* __restrict__ hmid)
{
    extern __shared__ float sm[];
    float* As = sm;
    float4* Ws4 = (float4*)(sm + 32 * HH);
    int tid = threadIdx.x;
    int row0 = blockIdx.x * 32;

    #pragma unroll
    for (int idx = tid; idx < 32 * 32; idx += 256) {
        float4 a = ((const float4*)(attn + row0 * HH))[idx];
        float4 q = ((const float4*)(Qin  + row0 * HH))[idx];
        a.x += q.x; a.y += q.y; a.z += q.z; a.w += q.w;
        ((float4*)As)[idx] = a;
    }
    const float4* Wsrc = (const float4*)(WTbase + WT_OFF(3, layer));
    #pragma unroll
    for (int idx = tid; idx < 4096; idx += 256)
        Ws4[idx] = Wsrc[idx];
    __syncthreads();
    ln_tile(As, ln_g, ln_b, seqs2, row0);
    __syncthreads();

    int cg = tid & 31, rg = tid >> 5;
    float4 acc[4];
    #pragma unroll
    for (int i = 0; i < 4; i++) acc[i] = make_float4(0.f, 0.f, 0.f, 0.f);
    gemm_core(As, Ws4, cg, rg, acc);

    float4 bs = ((const float4*)b1)[cg];
    #pragma unroll
    for (int i = 0; i < 4; i++) {
        int m = row0 + rg * 4 + i;
        float4 v = acc[i];
        v.x = fmaxf(v.x + bs.x, 0.f); v.y = fmaxf(v.y + bs.y, 0.f);
        v.z = fmaxf(v.z + bs.z, 0.f); v.w = fmaxf(v.w + bs.w, 0.f);
        ((float4*)(hmid + m * HH))[cg] = v;
    }
}

// ---------------------------------------------------------------------------
// FFN2: seqs_out = (hmid @ W2T + b2 + seqs2) * padmask
// ---------------------------------------------------------------------------
__global__ void __launch_bounds__(256)
ffn2_kernel(const float* __restrict__ hmid, const float* __restrict__ WTbase, int layer,
            const float* __restrict__ b2, const float* __restrict__ seqs2,
            const int* __restrict__ padidx, float* __restrict__ seqs_out)
{
    extern __shared__ float sm[];
    float* As = sm;
    float4* Ws4 = (float4*)(sm + 32 * HH);
    int tid = threadIdx.x;
    int row0 = blockIdx.x * 32;

    #pragma unroll
    for (int idx = tid; idx < 32 * 32; idx += 256)
        ((float4*)As)[idx] = ((const float4*)(hmid + row0 * HH))[idx];
    const float4* Wsrc = (const float4*)(WTbase + WT_OFF(4, layer));
    #pragma unroll
    for (int idx = tid; idx < 4096; idx += 256)
        Ws4[idx] = Wsrc[idx];
    __syncthreads();

    int cg = tid & 31, rg = tid >> 5;
    float4 acc[4];
    #pragma unroll
    for (int i = 0; i < 4; i++) acc[i] = make_float4(0.f, 0.f, 0.f, 0.f);
    gemm_core(As, Ws4, cg, rg, acc);

    float4 bs = ((const float4*)b2)[cg];
    #pragma unroll
    for (int i = 0; i < 4; i++) {
        int m = row0 + rg * 4 + i;
        float4 v = acc[i];
        float4 r = ((const float4*)(seqs2 + m * HH))[cg];
        v.x += bs.x + r.x; v.y += bs.y + r.y; v.z += bs.z + r.z; v.w += bs.w + r.w;
        if (padidx[m] == 0) v = make_float4(0.f, 0.f, 0.f, 0.f);
        ((float4*)(seqs_out + m * HH))[cg] = v;
    }
}

// ---------------------------------------------------------------------------
// Attention v3: grid (2, NHH, BB); 256 threads; warp-per-query, no block
// barriers in the main loop. q interleaved by parity across the 2 q-blocks.
// ---------------------------------------------------------------------------
__global__ void __launch_bounds__(256)
attn_kernel(const float* __restrict__ Qb,
            const float* __restrict__ Kb,
            const float* __restrict__ Vb,
            const int*  __restrict__ tmat,
            const float* __restrict__ tmKg,
            const float* __restrict__ tmVg,
            const int*  __restrict__ log_seqs,
            float* __restrict__ outp)
{
    extern __shared__ float sm[];
    float* Ksh  = sm;                       // 200*36
    float* Vsh  = Ksh + LL * KROW;          // 200*36
    float* tmKs = Vsh + LL * KROW;          // 257*36
    float* tmVs = tmKs + TROWS * KROW;      // 257*36

    int qh = blockIdx.x;
    int h  = blockIdx.y;
    int b  = blockIdx.z;
    int tid = threadIdx.x;

    // stage K', V' head slices (KROW stride, float4)
    for (int idx = tid; idx < LL * 8; idx += 256) {
        int r = idx >> 3, d4 = idx & 7;
        ((float4*)(Ksh + r * KROW))[d4] =
            ((const float4*)(Kb + (b * LL + r) * HH + h * HSS))[d4];
        ((float4*)(Vsh + r * KROW))[d4] =
            ((const float4*)(Vb + (b * LL + r) * HH + h * HSS))[d4];
    }
    for (int idx = tid; idx < TROWS * 8; idx += 256) {
        int r = idx >> 3, d4 = idx & 7;
        ((float4*)(tmKs + r * KROW))[d4] =
            ((const float4*)(tmKg + r * HH + h * HSS))[d4];
        ((float4*)(tmVs + r * KROW))[d4] =
            ((const float4*)(tmVg + r * HH + h * HSS))[d4];
    }
    __syncthreads();

    const float scale = 0.17677669529663687f; // 1/sqrt(32)
    int w = tid >> 5, lane = tid & 31;

    for (int q = qh + 2 * w; q < LL; q += 16) {
        int rowq = b * LL + q;
        bool padq = (log_seqs[rowq] == 0);
        int kmax = padq ? LL : (q + 1);
        int nr = (kmax + 31) >> 5;           // <= 7

        float qv = Qb[rowq * HH + h * HSS + lane];
        float sr[7];
        int   tr[7];

        // --- scores ---
        for (int j = 0; j < nr; j++) {
            int k = 32 * j + lane;
            bool val = (k < kmax);
            int kc = val ? k : (kmax - 1);
            int t = tmat[rowq * LL + kc];
            tr[j] = t;
            const float4* kp = (const float4*)(Ksh + kc * KROW);
            const float4* tp = (const float4*)(tmKs + t * KROW);
            float acc = 0.f;
            #pragma unroll
            for (int d4 = 0; d4 < 8; d4++) {
                float4 kf = kp[d4], tf = tp[d4];
                acc = fmaf(__shfl_sync(FULLM, qv, 4 * d4 + 0), kf.x + tf.x, acc);
                acc = fmaf(__shfl_sync(FULLM, qv, 4 * d4 + 1), kf.y + tf.y, acc);
                acc = fmaf(__shfl_sync(FULLM, qv, 4 * d4 + 2), kf.z + tf.z, acc);
                acc = fmaf(__shfl_sync(FULLM, qv, 4 * d4 + 3), kf.w + tf.w, acc);
            }
            sr[j] = (val && !padq) ? acc * scale : NEGVAL;
        }

        // --- softmax (warp-local) ---
        float m = -INFINITY;
        for (int j = 0; j < nr; j++) m = fmaxf(m, sr[j]);
        #pragma unroll
        for (int o = 16; o; o >>= 1) m = fmaxf(m, __shfl_xor_sync(FULLM, m, o));
        float sum = 0.f;
        for (int j = 0; j < nr; j++) {
            int k = 32 * j + lane;
            float e = (k < kmax) ? __expf(sr[j] - m) : 0.f;
            sr[j] = e;
            sum += e;
        }
        #pragma unroll
        for (int o = 16; o; o >>= 1) sum += __shfl_xor_sync(FULLM, sum, o);
        float inv = 1.0f / sum;

        // --- value accumulation: lanes = d ---
        float acc = 0.f;
        for (int j = 0; j < nr; j++) {
            int kbase = 32 * j;
            #pragma unroll 8
            for (int kk = 0; kk < 32; kk++) {
                int k = kbase + kk;
                if (k >= kmax) break;
                float p = __shfl_sync(FULLM, sr[j], kk);
                int   t = __shfl_sync(FULLM, tr[j], kk);
                acc = fmaf(p, Vsh[k * KROW + lane] + tmVs[t * KROW + lane], acc);
            }
        }
        outp[rowq * HH + h * HSS + lane] = acc * inv;
    }
}

// ---------------------------------------------------------------------------
// Final LN + logits fused. One block per row, 128 threads.
// ---------------------------------------------------------------------------
__global__ void logits_kernel(const float* __restrict__ seqs,
                              const float* __restrict__ lnf_g,
                              const float* __restrict__ lnf_b,
                              const float* __restrict__ item_emb,
                              const int* __restrict__ pos_seqs,
                              const int* __restrict__ neg_seqs,
                              float* __restrict__ out)
{
    int row = blockIdx.x;
    int t = threadIdx.x;
    float x = seqs[row * HH + t];

    __shared__ float red[8];
    float s = x;
    #pragma unroll
    for (int o = 16; o; o >>= 1) s += __shfl_xor_sync(FULLM, s, o);
    if ((t & 31) == 0) red[t >> 5] = s;
    __syncthreads();
    float m = (red[0] + red[1] + red[2] + red[3]) * (1.0f / HH);
    float d = x - m;
    float s2 = d * d;
    #pragma unroll
    for (int o = 16; o; o >>= 1) s2 += __shfl_xor_sync(FULLM, s2, o);
    __syncthreads();
    if ((t & 31) == 0) red[t >> 5] = s2;
    __syncthreads();
    float v = (red[0] + red[1] + red[2] + red[3]) * (1.0f / HH);
    float f = d * rsqrtf(v + LN_EPS) * lnf_g[t] + lnf_b[t];

    float p = f * item_emb[pos_seqs[row] * HH + t];
    float n = f * item_emb[neg_seqs[row] * HH + t];
    #pragma unroll
    for (int o = 16; o; o >>= 1) {
        p += __shfl_xor_sync(FULLM, p, o);
        n += __shfl_xor_sync(FULLM, n, o);
    }
    __syncthreads();
    if ((t & 31) == 0) { red[t >> 5] = p; red[4 + (t >> 5)] = n; }
    __syncthreads();
    if (t == 0) out[row]         = red[0] + red[1] + red[2] + red[3];
    if (t == 1) out[M_TOT + row] = red[4] + red[5] + red[6] + red[7];
}

// ---------------------------------------------------------------------------
extern "C" void kernel_launch(void* const* d_in, const int* in_sizes, int n_in,
                              void* d_out, int out_size)
{
    const int*   log_seqs = (const int*)  d_in[0];
    const int*   tmat     = (const int*)  d_in[1];
    const int*   pos_seqs = (const int*)  d_in[2];
    const int*   neg_seqs = (const int*)  d_in[3];
    const float* item_emb = (const float*)d_in[5];
    const float* pos_K    = (const float*)d_in[6];
    const float* pos_V    = (const float*)d_in[7];
    const float* tm_K     = (const float*)d_in[8];
    const float* tm_V     = (const float*)d_in[9];
    const float* Wq = (const float*)d_in[10]; const float* bq = (const float*)d_in[11];
    const float* Wk = (const float*)d_in[12]; const float* bk = (const float*)d_in[13];
    const float* Wv = (const float*)d_in[14]; const float* bv = (const float*)d_in[15];
    const float* ln1_g = (const float*)d_in[16]; const float* ln1_b = (const float*)d_in[17];
    const float* ln2_g = (const float*)d_in[18]; const float* ln2_b = (const float*)d_in[19];
    const float* W1 = (const float*)d_in[20]; const float* b1 = (const float*)d_in[21];
    const float* W2 = (const float*)d_in[22]; const float* b2 = (const float*)d_in[23];
    const float* lnf_g = (const float*)d_in[24]; const float* lnf_b = (const float*)d_in[25];
    float* out = (float*)d_out;

    float* S = nullptr;
    cudaGetSymbolAddress((void**)&S, d_scratch);
    float* WTbase = nullptr;
    cudaGetSymbolAddress((void**)&WTbase, d_wt);

    float* seqs  = S + 0 * MH;
    float* Qin   = S + 1 * MH;
    float* Qb    = S + 2 * MH;
    float* Kb    = S + 3 * MH;
    float* Vb    = S + 4 * MH;
    float* attn  = S + 5 * MH;
    float* seqs2 = S + 6 * MH;
    float* hmid  = S + 7 * MH;

    const int GEMM_SMEM = (32 * HH + HH * HH) * 4;                 // 80 KB
    const int ATTN_SMEM = (2 * LL * KROW + 2 * TROWS * KROW) * 4;  // ~131.6 KB
    cudaFuncSetAttribute(qkv_kernel,  cudaFuncAttributeMaxDynamicSharedMemorySize, GEMM_SMEM);
    cudaFuncSetAttribute(ffn1_kernel, cudaFuncAttributeMaxDynamicSharedMemorySize, GEMM_SMEM);
    cudaFuncSetAttribute(ffn2_kernel, cudaFuncAttributeMaxDynamicSharedMemorySize, GEMM_SMEM);
    cudaFuncSetAttribute(attn_kernel, cudaFuncAttributeMaxDynamicSharedMemorySize, ATTN_SMEM);

    transpose_w<<<dim3(4, 4, 10), dim3(32, 8)>>>(Wq, Wk, Wv, W1, W2, WTbase);
    embed_kernel<<<(MH + 255) / 256, 256>>>(log_seqs, item_emb, seqs);

    for (int i = 0; i < NBB; i++) {
        qkv_kernel<<<dim3(M_TOT / 32, 3), 256, GEMM_SMEM>>>(
            seqs, WTbase, i, bq + i * HH, bk + i * HH, bv + i * HH,
            pos_K, pos_V, ln1_g + i * HH, ln1_b + i * HH, Qin, Qb, Kb, Vb);
        attn_kernel<<<dim3(2, NHH, BB), 256, ATTN_SMEM>>>(
            Qb, Kb, Vb, tmat, tm_K, tm_V, log_seqs, attn);
        ffn1_kernel<<<M_TOT / 32, 256, GEMM_SMEM>>>(
            attn, Qin, WTbase, i, b1 + i * HH,
            ln2_g + i * HH, ln2_b + i * HH, seqs2, hmid);
        ffn2_kernel<<<M_TOT / 32, 256, GEMM_SMEM>>>(
            hmid, WTbase, i, b2 + i * HH, seqs2, log_seqs, seqs);
    }

    logits_kernel<<<M_TOT, 128>>>(seqs, lnf_g, lnf_b, item_emb,
                                  pos_seqs, neg_seqs, out);
}

// round 6
// speedup vs baseline: 4.2581x; 1.6633x over previous
#include <cuda_runtime.h>
#include <math.h>

#define BB 16
#define LL 200
#define HH 128
#define NHH 4
#define HSS 32
#define NBB 2
#define M_TOT (BB*LL)          // 3200
#define MH (M_TOT*HH)          // 409600
#define NEGVAL (-4294967295.0f)
#define LN_EPS 1e-8f
#define KROW 36                // padded shared row stride (floats), 16B-aligned
#define TROWS 257
#define FULLM 0xffffffffu
#define WT_OFF(type, layer) (((type)*2+(layer))*HH*HH)

// Scratch buffers + transposed weights
__device__ float d_scratch[8 * MH];
__device__ float d_wt[10 * HH * HH];

// ---- packed f32x2 helpers (sm_100+) --------------------------------------
__device__ __forceinline__ unsigned long long f2_pack(float lo, float hi) {
    unsigned long long r;
    asm("mov.b64 %0, {%1, %2};" : "=l"(r) : "f"(lo), "f"(hi));
    return r;
}
__device__ __forceinline__ void f2_unpack(unsigned long long v, float& lo, float& hi) {
    asm("mov.b64 {%0, %1}, %2;" : "=f"(lo), "=f"(hi) : "l"(v));
}
__device__ __forceinline__ unsigned long long f2_add(unsigned long long a, unsigned long long b) {
    unsigned long long r;
    asm("add.rn.f32x2 %0, %1, %2;" : "=l"(r) : "l"(a), "l"(b));
    return r;
}
__device__ __forceinline__ unsigned long long f2_fma(unsigned long long a, unsigned long long b, unsigned long long c) {
    unsigned long long r;
    asm("fma.rn.f32x2 %0, %1, %2, %3;" : "=l"(r) : "l"(a), "l"(b), "l"(c));
    return r;
}

// ---------------------------------------------------------------------------
__global__ void embed_kernel(const int* __restrict__ log_seqs,
                             const float* __restrict__ item_emb,
                             float* __restrict__ seqs)
{
    int i = blockIdx.x * blockDim.x + threadIdx.x;
    if (i >= MH) return;
    int row = i >> 7;
    int hc  = i & 127;
    int item = log_seqs[row];
    float v = item_emb[item * HH + hc] * 11.313708498984760390f; // sqrt(128)
    seqs[i] = (item == 0) ? 0.0f : v;
}

// ---------------------------------------------------------------------------
// Transpose the 10 weight matrices [n][k] -> WT [k][n]
// ---------------------------------------------------------------------------
__global__ void transpose_w(const float* __restrict__ Wq, const float* __restrict__ Wk,
                            const float* __restrict__ Wv, const float* __restrict__ W1,
                            const float* __restrict__ W2, float* __restrict__ WT)
{
    __shared__ float t[32][33];
    int m = blockIdx.z;
    const float* src;
    switch (m >> 1) {
        case 0: src = Wq; break;
        case 1: src = Wk; break;
        case 2: src = Wv; break;
        case 3: src = W1; break;
        default: src = W2; break;
    }
    src += (m & 1) * HH * HH;
    float* dst = WT + m * HH * HH;

    int x  = blockIdx.x * 32 + threadIdx.x;
    int y0 = blockIdx.y * 32;
    for (int i = threadIdx.y; i < 32; i += 8)
        t[i][threadIdx.x] = src[(y0 + i) * HH + x];
    __syncthreads();
    int xo  = blockIdx.y * 32 + threadIdx.x;
    int yo0 = blockIdx.x * 32;
    for (int i = threadIdx.y; i < 32; i += 8)
        dst[(yo0 + i) * HH + xo] = t[threadIdx.x][i];
}

// ---------------------------------------------------------------------------
// GEMM core: As [32][128] smem, Ws4 float4-view of WT tile [128][128] smem.
// ---------------------------------------------------------------------------
__device__ __forceinline__ void gemm_core(const float* As, const float4* Ws4,
                                          int cg, int rg, float4 acc[4])
{
    #pragma unroll 8
    for (int k4 = 0; k4 < 32; k4++) {
        float4 w0 = Ws4[(4 * k4 + 0) * 32 + cg];
        float4 w1 = Ws4[(4 * k4 + 1) * 32 + cg];
        float4 w2 = Ws4[(4 * k4 + 2) * 32 + cg];
        float4 w3 = Ws4[(4 * k4 + 3) * 32 + cg];
        #pragma unroll
        for (int i = 0; i < 4; i++) {
            float4 a = ((const float4*)(As + (rg * 4 + i) * HH))[k4];
            acc[i].x += a.x * w0.x + a.y * w1.x + a.z * w2.x + a.w * w3.x;
            acc[i].y += a.x * w0.y + a.y * w1.y + a.z * w2.y + a.w * w3.y;
            acc[i].z += a.x * w0.z + a.y * w1.z + a.z * w2.z + a.w * w3.z;
            acc[i].w += a.x * w0.w + a.y * w1.w + a.z * w2.w + a.w * w3.w;
        }
    }
}

// LayerNorm a 32x128 tile in shared (in place); optionally also write to gout.
__device__ __forceinline__ void ln_tile(float* As, const float* __restrict__ g,
                                        const float* __restrict__ bta,
                                        float* __restrict__ gout, int row0)
{
    int w = threadIdx.x >> 5, lane = threadIdx.x & 31;
    for (int r = w; r < 32; r += 8) {
        float* row = As + r * HH;
        float x0 = row[lane], x1 = row[lane + 32], x2 = row[lane + 64], x3 = row[lane + 96];
        float s = x0 + x1 + x2 + x3;
        #pragma unroll
        for (int o = 16; o; o >>= 1) s += __shfl_xor_sync(FULLM, s, o);
        float m = s * (1.0f / HH);
        float d0 = x0 - m, d1 = x1 - m, d2 = x2 - m, d3 = x3 - m;
        float v = d0 * d0 + d1 * d1 + d2 * d2 + d3 * d3;
        #pragma unroll
        for (int o = 16; o; o >>= 1) v += __shfl_xor_sync(FULLM, v, o);
        float rs = rsqrtf(v * (1.0f / HH) + LN_EPS);
        float y0 = d0 * rs * g[lane]      + bta[lane];
        float y1 = d1 * rs * g[lane + 32] + bta[lane + 32];
        float y2 = d2 * rs * g[lane + 64] + bta[lane + 64];
        float y3 = d3 * rs * g[lane + 96] + bta[lane + 96];
        row[lane] = y0; row[lane + 32] = y1; row[lane + 64] = y2; row[lane + 96] = y3;
        if (gout) {
            float* go = gout + (row0 + r) * HH;
            go[lane] = y0; go[lane + 32] = y1; go[lane + 64] = y2; go[lane + 96] = y3;
        }
    }
}

// ---------------------------------------------------------------------------
// QKV kernel: grid (100, 3). z=0: Q = LN1(seqs)@WqT+bq (also writes Qin).
// z=1: K = seqs@WkT+bk+posK. z=2: V = seqs@WvT+bv+posV.
// ---------------------------------------------------------------------------
__global__ void __launch_bounds__(256)
qkv_kernel(const float* __restrict__ seqs, const float* __restrict__ WTbase, int layer,
           const float* __restrict__ bq, const float* __restrict__ bk,
           const float* __restrict__ bv,
           const float* __restrict__ posK, const float* __restrict__ posV,
           const float* __restrict__ ln_g, const float* __restrict__ ln_b,
           float* __restrict__ Qin, float* __restrict__ Qb,
           float* __restrict__ Kb, float* __restrict__ Vb)
{
    extern __shared__ float sm[];
    float* As = sm;
    float4* Ws4 = (float4*)(sm + 32 * HH);
    int tid = threadIdx.x;
    int z = blockIdx.y;
    int row0 = blockIdx.x * 32;

    #pragma unroll
    for (int idx = tid; idx < 32 * 32; idx += 256)
        ((float4*)As)[idx] = ((const float4*)(seqs + row0 * HH))[idx];
    const float4* Wsrc = (const float4*)(WTbase + WT_OFF(z, layer));
    #pragma unroll
    for (int idx = tid; idx < 4096; idx += 256)
        Ws4[idx] = Wsrc[idx];
    __syncthreads();
    if (z == 0) {
        ln_tile(As, ln_g, ln_b, Qin, row0);
        __syncthreads();
    }

    int cg = tid & 31, rg = tid >> 5;
    float4 acc[4];
    #pragma unroll
    for (int i = 0; i < 4; i++) acc[i] = make_float4(0.f, 0.f, 0.f, 0.f);
    gemm_core(As, Ws4, cg, rg, acc);

    const float* bias = (z == 0) ? bq : (z == 1) ? bk : bv;
    const float* posadd = (z == 1) ? posK : (z == 2) ? posV : nullptr;
    float* C = (z == 0) ? Qb : (z == 1) ? Kb : Vb;
    float4 bs = ((const float4*)bias)[cg];
    #pragma unroll
    for (int i = 0; i < 4; i++) {
        int m = row0 + rg * 4 + i;
        float4 v = acc[i];
        v.x += bs.x; v.y += bs.y; v.z += bs.z; v.w += bs.w;
        if (posadd) {
            float4 p = ((const float4*)(posadd + (m % LL) * HH))[cg];
            v.x += p.x; v.y += p.y; v.z += p.z; v.w += p.w;
        }
        ((float4*)(C + m * HH))[cg] = v;
    }
}

// ---------------------------------------------------------------------------
// FFN1: seqs2 = LN2(attn + Qin); hmid = relu(seqs2 @ W1T + b1)
// ---------------------------------------------------------------------------
__global__ void __launch_bounds__(256)
ffn1_kernel(const float* __restrict__ attn, const float* __restrict__ Qin,
            const float* __restrict__ WTbase, int layer,
            const float* __restrict__ b1,
            const float* __restrict__ ln_g, const float* __restrict__ ln_b,
            float* __restrict__ seqs2, float* __restrict__ hmid)
{
    extern __shared__ float sm[];
    float* As = sm;
    float4* Ws4 = (float4*)(sm + 32 * HH);
    int tid = threadIdx.x;
    int row0 = blockIdx.x * 32;

    #pragma unroll
    for (int idx = tid; idx < 32 * 32; idx += 256) {
        float4 a = ((const float4*)(attn + row0 * HH))[idx];
        float4 q = ((const float4*)(Qin  + row0 * HH))[idx];
        a.x += q.x; a.y += q.y; a.z += q.z; a.w += q.w;
        ((float4*)As)[idx] = a;
    }
    const float4* Wsrc = (const float4*)(WTbase + WT_OFF(3, layer));
    #pragma unroll
    for (int idx = tid; idx < 4096; idx += 256)
        Ws4[idx] = Wsrc[idx];
    __syncthreads();
    ln_tile(As, ln_g, ln_b, seqs2, row0);
    __syncthreads();

    int cg = tid & 31, rg = tid >> 5;
    float4 acc[4];
    #pragma unroll
    for (int i = 0; i < 4; i++) acc[i] = make_float4(0.f, 0.f, 0.f, 0.f);
    gemm_core(As, Ws4, cg, rg, acc);

    float4 bs = ((const float4*)b1)[cg];
    #pragma unroll
    for (int i = 0; i < 4; i++) {
        int m = row0 + rg * 4 + i;
        float4 v = acc[i];
        v.x = fmaxf(v.x + bs.x, 0.f); v.y = fmaxf(v.y + bs.y, 0.f);
        v.z = fmaxf(v.z + bs.z, 0.f); v.w = fmaxf(v.w + bs.w, 0.f);
        ((float4*)(hmid + m * HH))[cg] = v;
    }
}

// ---------------------------------------------------------------------------
// FFN2: seqs_out = (hmid @ W2T + b2 + seqs2) * padmask
// ---------------------------------------------------------------------------
__global__ void __launch_bounds__(256)
ffn2_kernel(const float* __restrict__ hmid, const float* __restrict__ WTbase, int layer,
            const float* __restrict__ b2, const float* __restrict__ seqs2,
            const int* __restrict__ padidx, float* __restrict__ seqs_out)
{
    extern __shared__ float sm[];
    float* As = sm;
    float4* Ws4 = (float4*)(sm + 32 * HH);
    int tid = threadIdx.x;
    int row0 = blockIdx.x * 32;

    #pragma unroll
    for (int idx = tid; idx < 32 * 32; idx += 256)
        ((float4*)As)[idx] = ((const float4*)(hmid + row0 * HH))[idx];
    const float4* Wsrc = (const float4*)(WTbase + WT_OFF(4, layer));
    #pragma unroll
    for (int idx = tid; idx < 4096; idx += 256)
        Ws4[idx] = Wsrc[idx];
    __syncthreads();

    int cg = tid & 31, rg = tid >> 5;
    float4 acc[4];
    #pragma unroll
    for (int i = 0; i < 4; i++) acc[i] = make_float4(0.f, 0.f, 0.f, 0.f);
    gemm_core(As, Ws4, cg, rg, acc);

    float4 bs = ((const float4*)b2)[cg];
    #pragma unroll
    for (int i = 0; i < 4; i++) {
        int m = row0 + rg * 4 + i;
        float4 v = acc[i];
        float4 r = ((const float4*)(seqs2 + m * HH))[cg];
        v.x += bs.x + r.x; v.y += bs.y + r.y; v.z += bs.z + r.z; v.w += bs.w + r.w;
        if (padidx[m] == 0) v = make_float4(0.f, 0.f, 0.f, 0.f);
        ((float4*)(seqs_out + m * HH))[cg] = v;
    }
}

// ---------------------------------------------------------------------------
// Attention v4: grid (2, NHH, BB); 512 threads (16 warps); warp-per-query.
// Q hoisted into registers once per query; score dot uses packed f32x2.
// ---------------------------------------------------------------------------
__global__ void __launch_bounds__(512)
attn_kernel(const float* __restrict__ Qb,
            const float* __restrict__ Kb,
            const float* __restrict__ Vb,
            const int*  __restrict__ tmat,
            const float* __restrict__ tmKg,
            const float* __restrict__ tmVg,
            const int*  __restrict__ log_seqs,
            float* __restrict__ outp)
{
    extern __shared__ float sm[];
    float* Ksh  = sm;                       // 200*36
    float* Vsh  = Ksh + LL * KROW;          // 200*36
    float* tmKs = Vsh + LL * KROW;          // 257*36
    float* tmVs = tmKs + TROWS * KROW;      // 257*36

    int qh = blockIdx.x;
    int h  = blockIdx.y;
    int b  = blockIdx.z;
    int tid = threadIdx.x;

    for (int idx = tid; idx < LL * 8; idx += 512) {
        int r = idx >> 3, d4 = idx & 7;
        ((float4*)(Ksh + r * KROW))[d4] =
            ((const float4*)(Kb + (b * LL + r) * HH + h * HSS))[d4];
        ((float4*)(Vsh + r * KROW))[d4] =
            ((const float4*)(Vb + (b * LL + r) * HH + h * HSS))[d4];
    }
    for (int idx = tid; idx < TROWS * 8; idx += 512) {
        int r = idx >> 3, d4 = idx & 7;
        ((float4*)(tmKs + r * KROW))[d4] =
            ((const float4*)(tmKg + r * HH + h * HSS))[d4];
        ((float4*)(tmVs + r * KROW))[d4] =
            ((const float4*)(tmVg + r * HH + h * HSS))[d4];
    }
    __syncthreads();

    const float scale = 0.17677669529663687f; // 1/sqrt(32)
    int w = tid >> 5, lane = tid & 31;

    for (int q = qh + 2 * w; q < LL; q += 32) {
        int rowq = b * LL + q;
        bool padq = (log_seqs[rowq] == 0);
        int kmax = padq ? LL : (q + 1);
        int nr = (kmax + 31) >> 5;           // <= 7

        // hoist Q into packed f32x2 registers (one broadcast pass)
        float qv = Qb[rowq * HH + h * HSS + lane];
        unsigned long long qp2[16];
        #pragma unroll
        for (int i = 0; i < 16; i++) {
            float q0 = __shfl_sync(FULLM, qv, 2 * i);
            float q1 = __shfl_sync(FULLM, qv, 2 * i + 1);
            qp2[i] = f2_pack(q0, q1);
        }

        float sr[7];
        int   tr[7];

        // --- scores: lane owns key k = 32j + lane ---
        for (int j = 0; j < nr; j++) {
            int k = 32 * j + lane;
            bool val = (k < kmax);
            int kc = val ? k : (kmax - 1);
            int t = tmat[rowq * LL + kc];
            tr[j] = t;
            const ulonglong2* kp = (const ulonglong2*)(Ksh + kc * KROW);
            const ulonglong2* tp = (const ulonglong2*)(tmKs + t * KROW);
            unsigned long long acc2 = f2_pack(0.f, 0.f);
            #pragma unroll
            for (int d4 = 0; d4 < 8; d4++) {
                ulonglong2 kf = kp[d4];
                ulonglong2 tf = tp[d4];
                acc2 = f2_fma(qp2[2 * d4 + 0], f2_add(kf.x, tf.x), acc2);
                acc2 = f2_fma(qp2[2 * d4 + 1], f2_add(kf.y, tf.y), acc2);
            }
            float a0, a1;
            f2_unpack(acc2, a0, a1);
            sr[j] = (val && !padq) ? (a0 + a1) * scale : NEGVAL;
        }

        // --- softmax (warp-local) ---
        float m = -INFINITY;
        for (int j = 0; j < nr; j++) m = fmaxf(m, sr[j]);
        #pragma unroll
        for (int o = 16; o; o >>= 1) m = fmaxf(m, __shfl_xor_sync(FULLM, m, o));
        float sum = 0.f;
        for (int j = 0; j < nr; j++) {
            int k = 32 * j + lane;
            float e = (k < kmax) ? __expf(sr[j] - m) : 0.f;
            sr[j] = e;
            sum += e;
        }
        #pragma unroll
        for (int o = 16; o; o >>= 1) sum += __shfl_xor_sync(FULLM, sum, o);
        float inv = 1.0f / sum;

        // --- value accumulation: lanes = d ---
        float acc = 0.f;
        for (int j = 0; j < nr; j++) {
            int kbase = 32 * j;
            int cnt = kmax - kbase;
            if (cnt > 32) cnt = 32;
            #pragma unroll 8
            for (int kk = 0; kk < cnt; kk++) {
                int k = kbase + kk;
                float p = __shfl_sync(FULLM, sr[j], kk);
                int   t = __shfl_sync(FULLM, tr[j], kk);
                acc = fmaf(p, Vsh[k * KROW + lane] + tmVs[t * KROW + lane], acc);
            }
        }
        outp[rowq * HH + h * HSS + lane] = acc * inv;
    }
}

// ---------------------------------------------------------------------------
// Final LN + logits fused. One block per row, 128 threads.
// ---------------------------------------------------------------------------
__global__ void logits_kernel(const float* __restrict__ seqs,
                              const float* __restrict__ lnf_g,
                              const float* __restrict__ lnf_b,
                              const float* __restrict__ item_emb,
                              const int* __restrict__ pos_seqs,
                              const int* __restrict__ neg_seqs,
                              float* __restrict__ out)
{
    int row = blockIdx.x;
    int t = threadIdx.x;
    float x = seqs[row * HH + t];

    __shared__ float red[8];
    float s = x;
    #pragma unroll
    for (int o = 16; o; o >>= 1) s += __shfl_xor_sync(FULLM, s, o);
    if ((t & 31) == 0) red[t >> 5] = s;
    __syncthreads();
    float m = (red[0] + red[1] + red[2] + red[3]) * (1.0f / HH);
    float d = x - m;
    float s2 = d * d;
    #pragma unroll
    for (int o = 16; o; o >>= 1) s2 += __shfl_xor_sync(FULLM, s2, o);
    __syncthreads();
    if ((t & 31) == 0) red[t >> 5] = s2;
    __syncthreads();
    float v = (red[0] + red[1] + red[2] + red[3]) * (1.0f / HH);
    float f = d * rsqrtf(v + LN_EPS) * lnf_g[t] + lnf_b[t];

    float p = f * item_emb[pos_seqs[row] * HH + t];
    float n = f * item_emb[neg_seqs[row] * HH + t];
    #pragma unroll
    for (int o = 16; o; o >>= 1) {
        p += __shfl_xor_sync(FULLM, p, o);
        n += __shfl_xor_sync(FULLM, n, o);
    }
    __syncthreads();
    if ((t & 31) == 0) { red[t >> 5] = p; red[4 + (t >> 5)] = n; }
    __syncthreads();
    if (t == 0) out[row]         = red[0] + red[1] + red[2] + red[3];
    if (t == 1) out[M_TOT + row] = red[4] + red[5] + red[6] + red[7];
}

// ---------------------------------------------------------------------------
extern "C" void kernel_launch(void* const* d_in, const int* in_sizes, int n_in,
                              void* d_out, int out_size)
{
    const int*   log_seqs = (const int*)  d_in[0];
    const int*   tmat     = (const int*)  d_in[1];
    const int*   pos_seqs = (const int*)  d_in[2];
    const int*   neg_seqs = (const int*)  d_in[3];
    const float* item_emb = (const float*)d_in[5];
    const float* pos_K    = (const float*)d_in[6];
    const float* pos_V    = (const float*)d_in[7];
    const float* tm_K     = (const float*)d_in[8];
    const float* tm_V     = (const float*)d_in[9];
    const float* Wq = (const float*)d_in[10]; const float* bq = (const float*)d_in[11];
    const float* Wk = (const float*)d_in[12]; const float* bk = (const float*)d_in[13];
    const float* Wv = (const float*)d_in[14]; const float* bv = (const float*)d_in[15];
    const float* ln1_g = (const float*)d_in[16]; const float* ln1_b = (const float*)d_in[17];
    const float* ln2_g = (const float*)d_in[18]; const float* ln2_b = (const float*)d_in[19];
    const float* W1 = (const float*)d_in[20]; const float* b1 = (const float*)d_in[21];
    const float* W2 = (const float*)d_in[22]; const float* b2 = (const float*)d_in[23];
    const float* lnf_g = (const float*)d_in[24]; const float* lnf_b = (const float*)d_in[25];
    float* out = (float*)d_out;

    float* S = nullptr;
    cudaGetSymbolAddress((void**)&S, d_scratch);
    float* WTbase = nullptr;
    cudaGetSymbolAddress((void**)&WTbase, d_wt);

    float* seqs  = S + 0 * MH;
    float* Qin   = S + 1 * MH;
    float* Qb    = S + 2 * MH;
    float* Kb    = S + 3 * MH;
    float* Vb    = S + 4 * MH;
    float* attn  = S + 5 * MH;
    float* seqs2 = S + 6 * MH;
    float* hmid  = S + 7 * MH;

    const int GEMM_SMEM = (32 * HH + HH * HH) * 4;                 // 80 KB
    const int ATTN_SMEM = (2 * LL * KROW + 2 * TROWS * KROW) * 4;  // ~131.6 KB
    cudaFuncSetAttribute(qkv_kernel,  cudaFuncAttributeMaxDynamicSharedMemorySize, GEMM_SMEM);
    cudaFuncSetAttribute(ffn1_kernel, cudaFuncAttributeMaxDynamicSharedMemorySize, GEMM_SMEM);
    cudaFuncSetAttribute(ffn2_kernel, cudaFuncAttributeMaxDynamicSharedMemorySize, GEMM_SMEM);
    cudaFuncSetAttribute(attn_kernel, cudaFuncAttributeMaxDynamicSharedMemorySize, ATTN_SMEM);

    transpose_w<<<dim3(4, 4, 10), dim3(32, 8)>>>(Wq, Wk, Wv, W1, W2, WTbase);
    embed_kernel<<<(MH + 255) / 256, 256>>>(log_seqs, item_emb, seqs);

    for (int i = 0; i < NBB; i++) {
        qkv_kernel<<<dim3(M_TOT / 32, 3), 256, GEMM_SMEM>>>(
            seqs, WTbase, i, bq + i * HH, bk + i * HH, bv + i * HH,
            pos_K, pos_V, ln1_g + i * HH, ln1_b + i * HH, Qin, Qb, Kb, Vb);
        attn_kernel<<<dim3(2, NHH, BB), 512, ATTN_SMEM>>>(
            Qb, Kb, Vb, tmat, tm_K, tm_V, log_seqs, attn);
        ffn1_kernel<<<M_TOT / 32, 256, GEMM_SMEM>>>(
            attn, Qin, WTbase, i, b1 + i * HH,
            ln2_g + i * HH, ln2_b + i * HH, seqs2, hmid);
        ffn2_kernel<<<M_TOT / 32, 256, GEMM_SMEM>>>(
            hmid, WTbase, i, b2 + i * HH, seqs2, log_seqs, seqs);
    }

    logits_kernel<<<M_TOT, 128>>>(seqs, lnf_g, lnf_b, item_emb,
                                  pos_seqs, neg_seqs, out);
}